// round 8
// baseline (speedup 1.0000x reference)
#include <cuda_runtime.h>

// Problem constants
#define BATCH 16
#define SEQ   720
#define CIN   321
#define NORD  64
#define PRED  720
#define M_TOT (BATCH*CIN)        // 5136
#define MPAD  5376               // 21*256 = 42*128
#define TSPLIT 12
#define TCHUNK 60                // 720/12
#define KCH   20                 // k-chunk in gemm1 (3 per TCHUNK)
#define ROW_STRIDE (SEQ*CIN)     // 231120
#define TSTRIDE 68               // padded transpose stride (floats)
#define NCHAIN 32                // chains in buildk (A^32 stride)
#define OSTR  132                // epilogue staging stride

typedef unsigned long long ull;

// ---------------- packed f32x2 helpers ----------------
__device__ __forceinline__ ull fma2(ull a, ull b, ull c) {
    ull d;
    asm("fma.rn.f32x2 %0, %1, %2, %3;" : "=l"(d) : "l"(a), "l"(b), "l"(c));
    return d;
}
__device__ __forceinline__ ull dup2(float x) {
    ull d; asm("mov.b64 %0, {%1, %1};" : "=l"(d) : "f"(x)); return d;
}
__device__ __forceinline__ float2 upk2(ull v) {
    float x, y; asm("mov.b64 {%0, %1}, %2;" : "=f"(x), "=f"(y) : "l"(v));
    return make_float2(x, y);
}

// ---------------- device scratch ----------------
__device__ float g_Kt   [PRED*NORD];        // Kt[t][n] = (A^(719-t) B)[n]
__device__ float g_Spart[NCHAIN*NORD];
__device__ float g_EWT  [NORD*PRED];        // (E @ W) transposed: [n][p]
__device__ float g_eb   [PRED];             // E @ b_mlp
__device__ float g_XK   [TSPLIT][MPAD*NORD];
__device__ float g_XKpT [NORD*MPAD];        // alpha-folded GEMM2 operand, [n][m]
__device__ float g_rsum [TSPLIT][MPAD];
__device__ float g_rsq  [TSPLIT][MPAD];
__device__ float g_mean [MPAD];
__device__ float g_std  [MPAD];

// ============================================================================
// buildk: blocks 0..31: A^2..A^32 powers (redundant per block), seed A^r B,
// 23-step chain with A^32. Blocks 32..47: EWT = (E@W)^T and eb = E@b.
// ============================================================================
__global__ void __launch_bounds__(256) buildk_kernel(
    const float* __restrict__ A, const float* __restrict__ Bv,
    const float* __restrict__ E, const float* __restrict__ W,
    const float* __restrict__ bm)
{
    extern __shared__ float sh[];
    const int tid = threadIdx.x;
    const int bid = blockIdx.x;

    if (bid >= NCHAIN) {
        float* Wsh = sh;               // 4096
        float* Esh = sh + 4096;        // 45*64
        __shared__ float bsh[NORD];
        const int e = bid - NCHAIN;
        for (int i = tid; i < NORD*NORD; i += 256) Wsh[i] = W[i];
        for (int i = tid; i < 45*NORD; i += 256)  Esh[i] = E[e*45*NORD + i];
        if (tid < NORD) bsh[tid] = bm[tid];
        __syncthreads();
        for (int idx = tid; idx < 45*NORD; idx += 256) {
            const int pl = idx >> 6, m = idx & 63;
            float a0 = 0.f, a1 = 0.f;
#pragma unroll
            for (int n = 0; n < NORD; n += 2) {
                a0 += Esh[pl*NORD + n    ] * Wsh[(n    )*NORD + m];
                a1 += Esh[pl*NORD + n + 1] * Wsh[(n + 1)*NORD + m];
            }
            g_EWT[(size_t)m*PRED + e*45 + pl] = a0 + a1;
        }
        if (tid < 45) {
            float a = 0.f;
#pragma unroll
            for (int n = 0; n < NORD; n++) a += Esh[tid*NORD + n] * bsh[n];
            g_eb[e*45 + tid] = a;
        }
        return;
    }

    float* TP[6];
#pragma unroll
    for (int i = 0; i < 6; i++) TP[i] = sh + i * NORD * TSTRIDE;
    float* N0 = sh + 6 * NORD * TSTRIDE;
    float* N1 = N0 + NORD*NORD;
    __shared__ float vsh[NORD];
    __shared__ float pb[256];

    for (int i = tid; i < NORD*NORD; i += 256) N0[i] = A[i];
    __syncthreads();
    for (int i = tid; i < NORD*NORD; i += 256)
        TP[0][(i & 63)*TSTRIDE + (i >> 6)] = N0[i];
    __syncthreads();

    float* srcN = N0;
    float* dstN = N1;
    const int ig = tid >> 4;
    const int jg = tid & 15;
#pragma unroll
    for (int s = 0; s < 5; s++) {
        const float* srcT = TP[s];
        ull acc2[4][2];
#pragma unroll
        for (int ii = 0; ii < 4; ii++) { acc2[ii][0] = 0ull; acc2[ii][1] = 0ull; }
#pragma unroll 8
        for (int k = 0; k < NORD; k++) {
            const float4 a = *(const float4*)&srcT[k*TSTRIDE + ig*4];
            const ulonglong2 b = *(const ulonglong2*)&srcN[k*NORD + jg*4];
            float av[4] = {a.x, a.y, a.z, a.w};
#pragma unroll
            for (int ii = 0; ii < 4; ii++) {
                const ull am = dup2(av[ii]);
                acc2[ii][0] = fma2(am, b.x, acc2[ii][0]);
                acc2[ii][1] = fma2(am, b.y, acc2[ii][1]);
            }
        }
#pragma unroll
        for (int ii = 0; ii < 4; ii++) {
            const float2 lo = upk2(acc2[ii][0]);
            const float2 hi = upk2(acc2[ii][1]);
            float4 v; v.x = lo.x; v.y = lo.y; v.z = hi.x; v.w = hi.y;
            *(float4*)&dstN[(ig*4 + ii)*NORD + jg*4] = v;
        }
        __syncthreads();
        for (int i = tid; i < NORD*NORD; i += 256)
            TP[s+1][(i & 63)*TSTRIDE + (i >> 6)] = dstN[i];
        __syncthreads();
        float* tmp = srcN; srcN = dstN; dstN = tmp;
    }

    const int r = bid;
    const int n = tid & 63, q = tid >> 6;

    if (tid < NORD) vsh[tid] = Bv[tid];
    __syncthreads();
#pragma unroll
    for (int b = 0; b < 5; b++) {
        if ((r >> b) & 1) {
            float p = 0.f;
#pragma unroll
            for (int kk = 0; kk < 16; kk++) {
                const int k = q*16 + kk;
                p += TP[b][k*TSTRIDE + n] * vsh[k];
            }
            pb[tid] = p;
            __syncthreads();
            if (tid < NORD) vsh[tid] = pb[tid] + pb[tid+64] + pb[tid+128] + pb[tid+192];
            __syncthreads();
        }
    }

    const float* T32 = TP[5];
    float sacc = 0.f;
    for (int j = 0; j < 23; j++) {
        const int s_exp = 32*j + r;
        if (s_exp < 720 && tid < NORD) {
            const float u = vsh[tid];
            g_Kt[(719 - s_exp)*NORD + tid] = u;
            sacc += u;
        }
        if (j < 22) {
            float p = 0.f;
#pragma unroll
            for (int kk = 0; kk < 16; kk++) {
                const int k = q*16 + kk;
                p += T32[k*TSTRIDE + n] * vsh[k];
            }
            pb[tid] = p;
            __syncthreads();
            if (tid < NORD) vsh[tid] = pb[tid] + pb[tid+64] + pb[tid+128] + pb[tid+192];
            __syncthreads();
        }
    }
    if (tid < NORD) g_Spart[r*NORD + tid] = sacc;
}

// ============================================================================
// GEMM1: XK[m,n] = sum_t x[m,t] * Kt[t,n], fused mean/var partials.
// grid (21, 12), block 128. Mtile=256, N=64. Per thread 16m x 8n (m-pairs).
// tm = tid>>3 in [0,16) -> m = mbase + tm*16 + 0..15 (phase-broadcast loads)
// tn = tid&7          -> n = c*32 + tn*4 + 0..3  (16B lane stride: no conflicts)
// ============================================================================
__global__ void __launch_bounds__(128) gemm1_kernel(const float* __restrict__ x) {
    __shared__ __align__(16) float Xs[KCH][256];
    __shared__ __align__(16) float Ks[KCH][64];

    const int tid   = threadIdx.x;
    const int mbase = blockIdx.x * 256;
    const int h     = blockIdx.y;
    const int t0    = h * TCHUNK;

    // global-load lanes: two m columns per thread
    const int m0g = mbase + tid;
    const int m1g = mbase + 128 + tid;
    const int b0i = m0g / CIN, c0i = m0g - b0i * CIN;
    const int b1i = m1g / CIN, c1i = m1g - b1i * CIN;
    const float* xrow0 = x + (size_t)b0i * ROW_STRIDE + c0i;
    const float* xrow1 = x + (size_t)b1i * ROW_STRIDE + c1i;
    const bool v0 = (m0g < M_TOT), v1 = (m1g < M_TOT);

    const int tm = tid >> 3;     // 0..15
    const int tn = tid & 7;      // 0..7
    const int tm16 = tm * 16;
    const int tn4  = tn * 4;

    ull acc[8][8];               // [m-pair][nj]
#pragma unroll
    for (int i = 0; i < 8; i++)
#pragma unroll
        for (int j = 0; j < 8; j++) acc[i][j] = 0ull;
    float ps0 = 0.f, pq0 = 0.f, ps1 = 0.f, pq1 = 0.f;

    for (int kt = 0; kt < TCHUNK/KCH; kt++) {
        const int tb = t0 + kt*KCH;
#pragma unroll
        for (int tt = 0; tt < KCH; tt++) {
            float xv0 = v0 ? xrow0[(tb + tt) * CIN] : 0.f;
            float xv1 = v1 ? xrow1[(tb + tt) * CIN] : 0.f;
            Xs[tt][tid]       = xv0;
            Xs[tt][tid + 128] = xv1;
            ps0 += xv0; pq0 += xv0*xv0;
            ps1 += xv1; pq1 += xv1*xv1;
        }
#pragma unroll
        for (int i = 0; i < (KCH*64)/128; i++) {
            const int idx = tid + i*128;
            const int tt = idx >> 6, nn = idx & 63;
            Ks[tt][nn] = g_Kt[(tb + tt) * NORD + nn];
        }
        __syncthreads();
#pragma unroll 4
        for (int tt = 0; tt < KCH; tt++) {
            const ulonglong2 a0 = *(const ulonglong2*)&Xs[tt][tm16];
            const ulonglong2 a1 = *(const ulonglong2*)&Xs[tt][tm16 + 4];
            const ulonglong2 a2 = *(const ulonglong2*)&Xs[tt][tm16 + 8];
            const ulonglong2 a3 = *(const ulonglong2*)&Xs[tt][tm16 + 12];
            const float4 b0 = *(const float4*)&Ks[tt][tn4];
            const float4 b1 = *(const float4*)&Ks[tt][tn4 + 32];
            const ull ap[8] = {a0.x, a0.y, a1.x, a1.y, a2.x, a2.y, a3.x, a3.y};
            const ull bd[8] = {dup2(b0.x), dup2(b0.y), dup2(b0.z), dup2(b0.w),
                               dup2(b1.x), dup2(b1.y), dup2(b1.z), dup2(b1.w)};
#pragma unroll
            for (int mp = 0; mp < 8; mp++)
#pragma unroll
                for (int nj = 0; nj < 8; nj++)
                    acc[mp][nj] = fma2(ap[mp], bd[nj], acc[mp][nj]);
        }
        __syncthreads();
    }

    float* xk = g_XK[h];
#pragma unroll
    for (int mp = 0; mp < 8; mp++) {
        const int m0 = mbase + tm16 + mp*2;
        float2 c[8];
#pragma unroll
        for (int nj = 0; nj < 8; nj++) c[nj] = upk2(acc[mp][nj]);
        float4 lo0; lo0.x = c[0].x; lo0.y = c[1].x; lo0.z = c[2].x; lo0.w = c[3].x;
        float4 lo1; lo1.x = c[4].x; lo1.y = c[5].x; lo1.z = c[6].x; lo1.w = c[7].x;
        float4 hi0; hi0.x = c[0].y; hi0.y = c[1].y; hi0.z = c[2].y; hi0.w = c[3].y;
        float4 hi1; hi1.x = c[4].y; hi1.y = c[5].y; hi1.z = c[6].y; hi1.w = c[7].y;
        *(float4*)&xk[(size_t)m0 * NORD + tn4]          = lo0;
        *(float4*)&xk[(size_t)m0 * NORD + tn4 + 32]     = lo1;
        *(float4*)&xk[(size_t)(m0+1) * NORD + tn4]      = hi0;
        *(float4*)&xk[(size_t)(m0+1) * NORD + tn4 + 32] = hi1;
    }
    g_rsum[h][m0g] = ps0;  g_rsq[h][m0g] = pq0;
    g_rsum[h][m1g] = ps1;  g_rsq[h][m1g] = pq1;
}

// ============================================================================
// fuse: reduce t-split partials + stats + S + alpha/beta fold + transpose.
// XKpT[n, m] = alpha_m * sum_h XK[h][m,n] + beta_m * S[n]
// grid MPAD/64, block 256.
// ============================================================================
__global__ void __launch_bounds__(256) fuse_kernel(const float* __restrict__ aw,
                                                   const float* __restrict__ ab) {
    __shared__ float TT[64*65];
    __shared__ float alpha_s[64], beta_s[64], Ssh[64];
    const int tid = threadIdx.x;
    const int mb  = blockIdx.x * 64;

    if (tid < 64) {
        const int m = mb + tid;
        float s = 0.f, qq = 0.f;
#pragma unroll
        for (int h = 0; h < TSPLIT; h++) { s += g_rsum[h][m]; qq += g_rsq[h][m]; }
        const float mean = s * (1.0f / 720.0f);
        const float var  = qq * (1.0f / 720.0f) - mean * mean;
        const float sd   = sqrtf(var + 1e-5f);
        const int bidx = m / CIN;
        const int ch   = m - bidx * CIN;
        const float al = aw[ch] / sd;
        alpha_s[tid] = al;
        beta_s[tid]  = ab[ch] - mean * al;
        g_mean[m] = mean;
        g_std[m]  = sd;
    } else if (tid < 128) {
        const int nn = tid - 64;
        float s = 0.f;
#pragma unroll
        for (int rr = 0; rr < NCHAIN; rr++) s += g_Spart[rr*NORD + nn];
        Ssh[nn] = s;
    }
    __syncthreads();

#pragma unroll
    for (int i = 0; i < 16; i++) {
        const int idx = i*256 + tid;           // 0..4095
        const int ml = idx >> 6, nn = idx & 63;
        float v = 0.f;
#pragma unroll
        for (int h = 0; h < TSPLIT; h++) v += g_XK[h][(size_t)(mb + ml)*NORD + nn];
        TT[nn*65 + ml] = alpha_s[ml]*v + beta_s[ml]*Ssh[nn];
    }
    __syncthreads();
#pragma unroll
    for (int i = 0; i < 16; i++) {
        const int idx = i*256 + tid;
        const int nn = idx >> 6, ml = idx & 63;
        g_XKpT[(size_t)nn*MPAD + mb + ml] = TT[nn*65 + ml];
    }
}

// ============================================================================
// GEMM2 + epilogue: pre[m,p] = sum_n XKpT[n,m] EWT[n,p] + eb[p];
// out = (pre - ab)/(aw+1e-10)*sd + mean.
// grid (42, 6), block 128. Mtile=128, Ptile=128, K=64 resident.
// Per thread 16m x 8p.  tm = tid&7 -> m = c*32 + tm*4 + 0..3 (16B lane stride,
// conflict-free); tp = tid>>3 -> p = tp*8 + 0..7 (phase-broadcast).
// ============================================================================
__global__ void __launch_bounds__(128) gemm2_kernel(float* __restrict__ out,
                                                    const float* __restrict__ aw,
                                                    const float* __restrict__ ab) {
    __shared__ __align__(16) float pool[16384];   // 64 KB
    float* Xs = pool;           // [64 k][128 m]
    float* Es = pool + 8192;    // [64 k][128 p]

    const int tid   = threadIdx.x;
    const int mbase = blockIdx.x * 128;
    const int pbase = blockIdx.y * 128;
    const int tm = tid & 7;
    const int tp = tid >> 3;     // 0..15
    const int tm4 = tm * 4;
    const int tp8 = tp * 8;

    // stage Xs: 16 float4 per thread, coalesced
#pragma unroll
    for (int i = 0; i < 16; i++) {
        const int idx = tid + i*128;            // 0..2047
        const int n = idx >> 5, mg = idx & 31;
        *(float4*)&Xs[n*128 + mg*4] =
            *(const float4*)&g_XKpT[(size_t)n*MPAD + mbase + mg*4];
    }
    // stage Es with p guard
#pragma unroll
    for (int i = 0; i < 16; i++) {
        const int idx = tid + i*128;
        const int n = idx >> 5, pg = idx & 31;
        const int p = pbase + pg*4;
        float4 v = make_float4(0.f, 0.f, 0.f, 0.f);
        if (p < PRED) v = *(const float4*)&g_EWT[(size_t)n*PRED + p];
        *(float4*)&Es[n*128 + pg*4] = v;
    }
    __syncthreads();

    ull acc[8][8];               // [m-pair][pj]
#pragma unroll
    for (int i = 0; i < 8; i++)
#pragma unroll
        for (int j = 0; j < 8; j++) acc[i][j] = 0ull;

#pragma unroll 4
    for (int k = 0; k < 64; k++) {
        const ulonglong2 a0 = *(const ulonglong2*)&Xs[k*128 + tm4];
        const ulonglong2 a1 = *(const ulonglong2*)&Xs[k*128 + tm4 + 32];
        const ulonglong2 a2 = *(const ulonglong2*)&Xs[k*128 + tm4 + 64];
        const ulonglong2 a3 = *(const ulonglong2*)&Xs[k*128 + tm4 + 96];
        const float4 e0 = *(const float4*)&Es[k*128 + tp8];
        const float4 e1 = *(const float4*)&Es[k*128 + tp8 + 4];
        const ull ap[8] = {a0.x, a0.y, a1.x, a1.y, a2.x, a2.y, a3.x, a3.y};
        const ull bd[8] = {dup2(e0.x), dup2(e0.y), dup2(e0.z), dup2(e0.w),
                           dup2(e1.x), dup2(e1.y), dup2(e1.z), dup2(e1.w)};
#pragma unroll
        for (int mp = 0; mp < 8; mp++)
#pragma unroll
            for (int pj = 0; pj < 8; pj++)
                acc[mp][pj] = fma2(ap[mp], bd[pj], acc[mp][pj]);
    }
    __syncthreads();   // done reading Xs/Es; pool reused as Os

    // epilogue in two 64-p rounds (Os = 64 x OSTR floats = 33 KB)
    float* Os = pool;
    float ebv[8];
#pragma unroll
    for (int pj = 0; pj < 8; pj++) {
        const int p = pbase + tp8 + pj;
        ebv[pj] = (p < PRED) ? g_eb[p] : 0.f;
    }
    const int myhalf = tp >> 3;          // this thread's p values live in one half

    const int ml_store = tid;            // store lane: m = mbase + tid
    const int m_st = mbase + ml_store;
    const int bi_st = m_st / CIN;
    const int ch_st = m_st - bi_st * CIN;
    float* ob = out + (size_t)bi_st * ROW_STRIDE + ch_st;

#pragma unroll
    for (int half = 0; half < 2; half++) {
        if (myhalf == half) {
#pragma unroll
            for (int mp = 0; mp < 8; mp++) {
                const int mloc = (mp >> 1)*32 + tm4 + (mp & 1)*2;
                float2 c[8];
#pragma unroll
                for (int pj = 0; pj < 8; pj++) c[pj] = upk2(acc[mp][pj]);
#pragma unroll
                for (int w = 0; w < 2; w++) {
                    const int m = mbase + mloc + w;
                    const float mean = g_mean[m];
                    const float sd   = g_std[m];
                    const int bi = m / CIN;
                    const int ch = m - bi * CIN;
                    const float abv = ab[ch];
                    const float scale = sd / (aw[ch] + 1e-10f);
                    const int plbase = tp8 - half*64;
#pragma unroll
                    for (int pj = 0; pj < 8; pj++) {
                        const float val = w ? c[pj].y : c[pj].x;
                        Os[(plbase + pj)*OSTR + mloc + w] =
                            (val + ebv[pj] - abv) * scale + mean;
                    }
                }
            }
        }
        __syncthreads();
        if (m_st < M_TOT) {
            const int p0 = pbase + half*64;
            const int plim = (PRED - p0 < 64) ? (PRED - p0) : 64;
            for (int pl = 0; pl < plim; pl++)
                ob[(size_t)(p0 + pl) * CIN] = Os[pl*OSTR + ml_store];
        }
        __syncthreads();
    }
}

// ---------------- launcher: 4 graph nodes ----------------
extern "C" void kernel_launch(void* const* d_in, const int* in_sizes, int n_in,
                              void* d_out, int out_size) {
    (void)in_sizes; (void)n_in; (void)out_size;
    const float* x  = (const float*)d_in[0];   // x_enc (16,720,321)
    const float* A  = (const float*)d_in[1];   // A (64,64)
    const float* Bv = (const float*)d_in[2];   // B_vec (64)
    const float* E  = (const float*)d_in[3];   // eval_matrix (720,64)
    const float* W  = (const float*)d_in[4];   // W_mlp (64,64)
    const float* bm = (const float*)d_in[5];   // b_mlp (64)
    const float* aw = (const float*)d_in[6];   // affine_weight (321)
    const float* ab = (const float*)d_in[7];   // affine_bias (321)
    float* out = (float*)d_out;

    const int buildk_smem = (6*NORD*TSTRIDE + 2*NORD*NORD) * (int)sizeof(float); // 137216
    cudaFuncSetAttribute(buildk_kernel, cudaFuncAttributeMaxDynamicSharedMemorySize, buildk_smem);

    buildk_kernel<<<NCHAIN + 16, 256, buildk_smem>>>(A, Bv, E, W, bm);
    gemm1_kernel<<<dim3(MPAD/256, TSPLIT), 128>>>(x);
    fuse_kernel<<<MPAD/64, 256>>>(aw, ab);
    gemm2_kernel<<<dim3(MPAD/128, PRED/128 + 1), 128>>>(out, aw, ab);
}

// round 9
// speedup vs baseline: 1.1647x; 1.1647x over previous
#include <cuda_runtime.h>

// Problem constants
#define BATCH 16
#define SEQ   720
#define CIN   321
#define NORD  64
#define PRED  720
#define M_TOT (BATCH*CIN)        // 5136
#define MPAD  5376               // 42*128 = 84*64
#define TSPLIT 12
#define TCHUNK 60                // 720/12
#define KCH   20                 // k-chunk in gemm1 (3 per TCHUNK)
#define ROW_STRIDE (SEQ*CIN)     // 231120
#define TSTRIDE 68               // padded transpose stride (floats)
#define NCHAIN 32                // chains in buildk (A^32 stride)
#define OSTR  67                 // epilogue staging stride (2-way max)

typedef unsigned long long ull;

// ---------------- packed f32x2 helpers ----------------
__device__ __forceinline__ ull fma2(ull a, ull b, ull c) {
    ull d;
    asm("fma.rn.f32x2 %0, %1, %2, %3;" : "=l"(d) : "l"(a), "l"(b), "l"(c));
    return d;
}
__device__ __forceinline__ ull dup2(float x) {
    ull d; asm("mov.b64 %0, {%1, %1};" : "=l"(d) : "f"(x)); return d;
}
__device__ __forceinline__ float2 upk2(ull v) {
    float x, y; asm("mov.b64 {%0, %1}, %2;" : "=f"(x), "=f"(y) : "l"(v));
    return make_float2(x, y);
}

// ---------------- device scratch ----------------
__device__ float g_Kt   [PRED*NORD];        // Kt[t][n] = (A^(719-t) B)[n]
__device__ float g_Spart[NCHAIN*NORD];
__device__ float g_EWT  [NORD*PRED];        // (E @ W) transposed: [n][p]
__device__ float g_eb   [PRED];             // E @ b_mlp
__device__ float g_XK   [TSPLIT][MPAD*NORD];
__device__ float g_XKpT [NORD*MPAD];        // alpha-folded GEMM2 operand, [n][m]
__device__ float g_rsum [TSPLIT][MPAD];
__device__ float g_rsq  [TSPLIT][MPAD];
__device__ float g_mean [MPAD];
__device__ float g_std  [MPAD];

// ============================================================================
// buildk: blocks 0..31: A^2..A^32 powers (redundant per block), seed A^r B,
// 23-step chain with A^32. Blocks 32..47: EWT = (E@W)^T and eb = E@b.
// ============================================================================
__global__ void __launch_bounds__(256) buildk_kernel(
    const float* __restrict__ A, const float* __restrict__ Bv,
    const float* __restrict__ E, const float* __restrict__ W,
    const float* __restrict__ bm)
{
    extern __shared__ float sh[];
    const int tid = threadIdx.x;
    const int bid = blockIdx.x;

    if (bid >= NCHAIN) {
        float* Wsh = sh;               // 4096
        float* Esh = sh + 4096;        // 45*64
        __shared__ float bsh[NORD];
        const int e = bid - NCHAIN;
        for (int i = tid; i < NORD*NORD; i += 256) Wsh[i] = W[i];
        for (int i = tid; i < 45*NORD; i += 256)  Esh[i] = E[e*45*NORD + i];
        if (tid < NORD) bsh[tid] = bm[tid];
        __syncthreads();
        for (int idx = tid; idx < 45*NORD; idx += 256) {
            const int pl = idx >> 6, m = idx & 63;
            float a0 = 0.f, a1 = 0.f;
#pragma unroll
            for (int n = 0; n < NORD; n += 2) {
                a0 += Esh[pl*NORD + n    ] * Wsh[(n    )*NORD + m];
                a1 += Esh[pl*NORD + n + 1] * Wsh[(n + 1)*NORD + m];
            }
            g_EWT[(size_t)m*PRED + e*45 + pl] = a0 + a1;
        }
        if (tid < 45) {
            float a = 0.f;
#pragma unroll
            for (int n = 0; n < NORD; n++) a += Esh[tid*NORD + n] * bsh[n];
            g_eb[e*45 + tid] = a;
        }
        return;
    }

    float* TP[6];
#pragma unroll
    for (int i = 0; i < 6; i++) TP[i] = sh + i * NORD * TSTRIDE;
    float* N0 = sh + 6 * NORD * TSTRIDE;
    float* N1 = N0 + NORD*NORD;
    __shared__ float vsh[NORD];
    __shared__ float pb[256];

    for (int i = tid; i < NORD*NORD; i += 256) N0[i] = A[i];
    __syncthreads();
    for (int i = tid; i < NORD*NORD; i += 256)
        TP[0][(i & 63)*TSTRIDE + (i >> 6)] = N0[i];
    __syncthreads();

    float* srcN = N0;
    float* dstN = N1;
    const int ig = tid >> 4;
    const int jg = tid & 15;
#pragma unroll
    for (int s = 0; s < 5; s++) {
        const float* srcT = TP[s];
        ull acc2[4][2];
#pragma unroll
        for (int ii = 0; ii < 4; ii++) { acc2[ii][0] = 0ull; acc2[ii][1] = 0ull; }
#pragma unroll 8
        for (int k = 0; k < NORD; k++) {
            const float4 a = *(const float4*)&srcT[k*TSTRIDE + ig*4];
            const ulonglong2 b = *(const ulonglong2*)&srcN[k*NORD + jg*4];
            float av[4] = {a.x, a.y, a.z, a.w};
#pragma unroll
            for (int ii = 0; ii < 4; ii++) {
                const ull am = dup2(av[ii]);
                acc2[ii][0] = fma2(am, b.x, acc2[ii][0]);
                acc2[ii][1] = fma2(am, b.y, acc2[ii][1]);
            }
        }
#pragma unroll
        for (int ii = 0; ii < 4; ii++) {
            const float2 lo = upk2(acc2[ii][0]);
            const float2 hi = upk2(acc2[ii][1]);
            float4 v; v.x = lo.x; v.y = lo.y; v.z = hi.x; v.w = hi.y;
            *(float4*)&dstN[(ig*4 + ii)*NORD + jg*4] = v;
        }
        __syncthreads();
        for (int i = tid; i < NORD*NORD; i += 256)
            TP[s+1][(i & 63)*TSTRIDE + (i >> 6)] = dstN[i];
        __syncthreads();
        float* tmp = srcN; srcN = dstN; dstN = tmp;
    }

    const int r = bid;
    const int n = tid & 63, q = tid >> 6;

    if (tid < NORD) vsh[tid] = Bv[tid];
    __syncthreads();
#pragma unroll
    for (int b = 0; b < 5; b++) {
        if ((r >> b) & 1) {
            float p = 0.f;
#pragma unroll
            for (int kk = 0; kk < 16; kk++) {
                const int k = q*16 + kk;
                p += TP[b][k*TSTRIDE + n] * vsh[k];
            }
            pb[tid] = p;
            __syncthreads();
            if (tid < NORD) vsh[tid] = pb[tid] + pb[tid+64] + pb[tid+128] + pb[tid+192];
            __syncthreads();
        }
    }

    const float* T32 = TP[5];
    float sacc = 0.f;
    for (int j = 0; j < 23; j++) {
        const int s_exp = 32*j + r;
        if (s_exp < 720 && tid < NORD) {
            const float u = vsh[tid];
            g_Kt[(719 - s_exp)*NORD + tid] = u;
            sacc += u;
        }
        if (j < 22) {
            float p = 0.f;
#pragma unroll
            for (int kk = 0; kk < 16; kk++) {
                const int k = q*16 + kk;
                p += T32[k*TSTRIDE + n] * vsh[k];
            }
            pb[tid] = p;
            __syncthreads();
            if (tid < NORD) vsh[tid] = pb[tid] + pb[tid+64] + pb[tid+128] + pb[tid+192];
            __syncthreads();
        }
    }
    if (tid < NORD) g_Spart[r*NORD + tid] = sacc;
}

// ============================================================================
// GEMM1: XK[m,n] = sum_t x[m,t] * Kt[t,n], fused mean/var partials.
// grid (42, 12), block 128. Mtile=128, N=64. Per thread 8m x 8n (4 m-pairs),
// register-prefetch pipelined inner loop.
// ============================================================================
__global__ void __launch_bounds__(128, 4) gemm1_kernel(const float* __restrict__ x) {
    __shared__ __align__(16) float Xs[KCH][128];
    __shared__ __align__(16) float Ks[KCH][64];

    const int tid   = threadIdx.x;
    const int mbase = blockIdx.x * 128;
    const int h     = blockIdx.y;
    const int t0    = h * TCHUNK;

    const int m_load = mbase + tid;
    const int bidx   = m_load / CIN;
    const int chl    = m_load - bidx * CIN;
    const float* xrow = x + (size_t)bidx * ROW_STRIDE + chl;
    const bool mval   = (m_load < M_TOT);

    const int tm = tid >> 3;     // 0..15 -> m = mbase + tm*8 + 0..7
    const int tn = tid & 7;      // n = tn*4 + {0..3} and {32..35}
    const int tm8 = tm * 8;
    const int tn4 = tn * 4;

    ull acc[4][8];               // [m-pair][nj]
#pragma unroll
    for (int i = 0; i < 4; i++)
#pragma unroll
        for (int j = 0; j < 8; j++) acc[i][j] = 0ull;
    float psum = 0.f, psq = 0.f;

    for (int kt = 0; kt < TCHUNK/KCH; kt++) {
        const int tb = t0 + kt*KCH;
#pragma unroll
        for (int tt = 0; tt < KCH; tt++) {
            float xv = mval ? xrow[(size_t)(tb + tt) * CIN] : 0.f;
            Xs[tt][tid] = xv;
            psum += xv;
            psq  += xv * xv;
        }
#pragma unroll
        for (int i = 0; i < (KCH*64)/128; i++) {
            const int idx = tid + i*128;
            const int tt = idx >> 6, nn = idx & 63;
            Ks[tt][nn] = g_Kt[(tb + tt) * NORD + nn];
        }
        __syncthreads();

        // software-pipelined inner loop
        ulonglong2 A0 = *(const ulonglong2*)&Xs[0][tm8];
        ulonglong2 A1 = *(const ulonglong2*)&Xs[0][tm8 + 4];
        float4 B0 = *(const float4*)&Ks[0][tn4];
        float4 B1 = *(const float4*)&Ks[0][tn4 + 32];
#pragma unroll 5
        for (int tt = 0; tt < KCH; tt++) {
            const int tnx = (tt + 1 < KCH) ? tt + 1 : 0;
            const ulonglong2 nA0 = *(const ulonglong2*)&Xs[tnx][tm8];
            const ulonglong2 nA1 = *(const ulonglong2*)&Xs[tnx][tm8 + 4];
            const float4 nB0 = *(const float4*)&Ks[tnx][tn4];
            const float4 nB1 = *(const float4*)&Ks[tnx][tn4 + 32];
            const ull ap[4] = {A0.x, A0.y, A1.x, A1.y};
            const ull bd[8] = {dup2(B0.x), dup2(B0.y), dup2(B0.z), dup2(B0.w),
                               dup2(B1.x), dup2(B1.y), dup2(B1.z), dup2(B1.w)};
#pragma unroll
            for (int mp = 0; mp < 4; mp++)
#pragma unroll
                for (int nj = 0; nj < 8; nj++)
                    acc[mp][nj] = fma2(ap[mp], bd[nj], acc[mp][nj]);
            A0 = nA0; A1 = nA1; B0 = nB0; B1 = nB1;
        }
        __syncthreads();
    }

    float* xk = g_XK[h];
#pragma unroll
    for (int mp = 0; mp < 4; mp++) {
        const int m0 = mbase + tm8 + mp*2;
        float2 c[8];
#pragma unroll
        for (int nj = 0; nj < 8; nj++) c[nj] = upk2(acc[mp][nj]);
        float4 lo0; lo0.x = c[0].x; lo0.y = c[1].x; lo0.z = c[2].x; lo0.w = c[3].x;
        float4 lo1; lo1.x = c[4].x; lo1.y = c[5].x; lo1.z = c[6].x; lo1.w = c[7].x;
        float4 hi0; hi0.x = c[0].y; hi0.y = c[1].y; hi0.z = c[2].y; hi0.w = c[3].y;
        float4 hi1; hi1.x = c[4].y; hi1.y = c[5].y; hi1.z = c[6].y; hi1.w = c[7].y;
        *(float4*)&xk[(size_t)m0 * NORD + tn4]          = lo0;
        *(float4*)&xk[(size_t)m0 * NORD + tn4 + 32]     = lo1;
        *(float4*)&xk[(size_t)(m0+1) * NORD + tn4]      = hi0;
        *(float4*)&xk[(size_t)(m0+1) * NORD + tn4 + 32] = hi1;
    }
    g_rsum[h][m_load] = psum;
    g_rsq [h][m_load] = psq;
}

// ============================================================================
// fuse: reduce t-split partials + stats + S + alpha/beta fold + transpose.
// XKpT[n, m] = alpha_m * sum_h XK[h][m,n] + beta_m * S[n]
// grid MPAD/64, block 256.
// ============================================================================
__global__ void __launch_bounds__(256) fuse_kernel(const float* __restrict__ aw,
                                                   const float* __restrict__ ab) {
    __shared__ float TT[64*65];
    __shared__ float alpha_s[64], beta_s[64], Ssh[64];
    const int tid = threadIdx.x;
    const int mb  = blockIdx.x * 64;

    if (tid < 64) {
        const int m = mb + tid;
        float s = 0.f, qq = 0.f;
#pragma unroll
        for (int h = 0; h < TSPLIT; h++) { s += g_rsum[h][m]; qq += g_rsq[h][m]; }
        const float mean = s * (1.0f / 720.0f);
        const float var  = qq * (1.0f / 720.0f) - mean * mean;
        const float sd   = sqrtf(var + 1e-5f);
        const int bidx = m / CIN;
        const int ch   = m - bidx * CIN;
        const float al = aw[ch] / sd;
        alpha_s[tid] = al;
        beta_s[tid]  = ab[ch] - mean * al;
        g_mean[m] = mean;
        g_std[m]  = sd;
    } else if (tid < 128) {
        const int nn = tid - 64;
        float s = 0.f;
#pragma unroll
        for (int rr = 0; rr < NCHAIN; rr++) s += g_Spart[rr*NORD + nn];
        Ssh[nn] = s;
    }
    __syncthreads();

#pragma unroll
    for (int i = 0; i < 16; i++) {
        const int idx = i*256 + tid;           // 0..4095
        const int ml = idx >> 6, nn = idx & 63;
        float v = 0.f;
#pragma unroll
        for (int h = 0; h < TSPLIT; h++) v += g_XK[h][(size_t)(mb + ml)*NORD + nn];
        TT[nn*65 + ml] = alpha_s[ml]*v + beta_s[ml]*Ssh[nn];
    }
    __syncthreads();
#pragma unroll
    for (int i = 0; i < 16; i++) {
        const int idx = i*256 + tid;
        const int nn = idx >> 6, ml = idx & 63;
        g_XKpT[(size_t)nn*MPAD + mb + ml] = TT[nn*65 + ml];
    }
}

// ============================================================================
// GEMM2 + epilogue: pre[m,p] = sum_n XKpT[n,m] EWT[n,p] + eb[p];
// out = (pre - ab)/(aw+1e-10)*sd + mean. Coalesced stores via smem staging.
// grid (84, 6), block 128. Mtile=64, Ptile=128, K=64 resident.
// Per thread 8m x 8p (4 m-pairs), register-prefetch pipelined inner loop.
// ============================================================================
__global__ void __launch_bounds__(128, 4) gemm2_kernel(float* __restrict__ out,
                                                       const float* __restrict__ aw,
                                                       const float* __restrict__ ab) {
    __shared__ __align__(16) float pool[12288];   // 48 KB
    float* Xs = pool;           // [64 k][64 m]
    float* Es = pool + 4096;    // [64 k][128 p]

    const int tid   = threadIdx.x;
    const int mbase = blockIdx.x * 64;
    const int pbase = blockIdx.y * 128;
    const int tm = tid & 7;      // m = mbase + tm*4 + {0..3, 32..35}
    const int tp = tid >> 3;     // p = pbase + tp*8 + 0..7
    const int tm4 = tm * 4;
    const int tp8 = tp * 8;

    // stage Xs: 8 float4 per thread, coalesced conflict-free
#pragma unroll
    for (int i = 0; i < 8; i++) {
        const int idx = tid + i*128;            // 0..1023
        const int n = idx >> 4, mg = idx & 15;
        *(float4*)&Xs[n*64 + mg*4] =
            *(const float4*)&g_XKpT[(size_t)n*MPAD + mbase + mg*4];
    }
    // stage Es with p guard: 16 float4 per thread
#pragma unroll
    for (int i = 0; i < 16; i++) {
        const int idx = tid + i*128;            // 0..2047
        const int n = idx >> 5, pg = idx & 31;
        const int p = pbase + pg*4;
        float4 v = make_float4(0.f, 0.f, 0.f, 0.f);
        if (p < PRED) v = *(const float4*)&g_EWT[(size_t)n*PRED + p];
        *(float4*)&Es[n*128 + pg*4] = v;
    }
    __syncthreads();

    ull acc[4][8];               // [m-pair][pj]
#pragma unroll
    for (int i = 0; i < 4; i++)
#pragma unroll
        for (int j = 0; j < 8; j++) acc[i][j] = 0ull;

    // software-pipelined K loop
    ulonglong2 A0 = *(const ulonglong2*)&Xs[tm4];
    ulonglong2 A1 = *(const ulonglong2*)&Xs[tm4 + 32];
    float4 B0 = *(const float4*)&Es[tp8];
    float4 B1 = *(const float4*)&Es[tp8 + 4];
#pragma unroll 8
    for (int k = 0; k < 64; k++) {
        const int kn = (k + 1) & 63;
        const ulonglong2 nA0 = *(const ulonglong2*)&Xs[kn*64 + tm4];
        const ulonglong2 nA1 = *(const ulonglong2*)&Xs[kn*64 + tm4 + 32];
        const float4 nB0 = *(const float4*)&Es[kn*128 + tp8];
        const float4 nB1 = *(const float4*)&Es[kn*128 + tp8 + 4];
        const ull ap[4] = {A0.x, A0.y, A1.x, A1.y};
        const ull bd[8] = {dup2(B0.x), dup2(B0.y), dup2(B0.z), dup2(B0.w),
                           dup2(B1.x), dup2(B1.y), dup2(B1.z), dup2(B1.w)};
#pragma unroll
        for (int mp = 0; mp < 4; mp++)
#pragma unroll
            for (int pj = 0; pj < 8; pj++)
                acc[mp][pj] = fma2(ap[mp], bd[pj], acc[mp][pj]);
        A0 = nA0; A1 = nA1; B0 = nB0; B1 = nB1;
    }
    __syncthreads();   // done reading Xs/Es; pool reused as Os

    // epilogue staged into Os[p_loc][m_loc] (stride OSTR=67)
    float* Os = pool;            // 128*67 = 8576 floats
    float ebv[8];
#pragma unroll
    for (int pj = 0; pj < 8; pj++) {
        const int p = pbase + tp8 + pj;
        ebv[pj] = (p < PRED) ? g_eb[p] : 0.f;
    }
#pragma unroll
    for (int mp = 0; mp < 4; mp++) {
        const int mloc0 = (mp < 2) ? (tm4 + 2*mp) : (tm4 + 32 + 2*(mp - 2));
        float2 c[8];
#pragma unroll
        for (int pj = 0; pj < 8; pj++) c[pj] = upk2(acc[mp][pj]);
#pragma unroll
        for (int w = 0; w < 2; w++) {
            const int m = mbase + mloc0 + w;
            const float mean = g_mean[m];
            const float sd   = g_std[m];
            const int bi = m / CIN;
            const int ch = m - bi * CIN;
            const float abv = ab[ch];
            const float scale = sd / (aw[ch] + 1e-10f);
#pragma unroll
            for (int pj = 0; pj < 8; pj++) {
                const float val = w ? c[pj].y : c[pj].x;
                Os[(tp8 + pj)*OSTR + mloc0 + w] = (val + ebv[pj] - abv) * scale + mean;
            }
        }
    }
    __syncthreads();

    // coalesced global store: lanes sweep m (64), two phases sweep p
    const int ml = tid & 63;
    const int ph = tid >> 6;            // 0/1
    const int m  = mbase + ml;
    if (m < M_TOT) {
        const int bi = m / CIN;
        const int ch = m - bi * CIN;
        float* ob = out + (size_t)bi * ROW_STRIDE + ch;
        const int plim = (PRED - pbase < 128) ? (PRED - pbase) : 128;
        for (int pl = ph; pl < plim; pl += 2)
            ob[(size_t)(pbase + pl) * CIN] = Os[pl*OSTR + ml];
    }
}

// ---------------- launcher: 4 graph nodes ----------------
extern "C" void kernel_launch(void* const* d_in, const int* in_sizes, int n_in,
                              void* d_out, int out_size) {
    (void)in_sizes; (void)n_in; (void)out_size;
    const float* x  = (const float*)d_in[0];   // x_enc (16,720,321)
    const float* A  = (const float*)d_in[1];   // A (64,64)
    const float* Bv = (const float*)d_in[2];   // B_vec (64)
    const float* E  = (const float*)d_in[3];   // eval_matrix (720,64)
    const float* W  = (const float*)d_in[4];   // W_mlp (64,64)
    const float* bm = (const float*)d_in[5];   // b_mlp (64)
    const float* aw = (const float*)d_in[6];   // affine_weight (321)
    const float* ab = (const float*)d_in[7];   // affine_bias (321)
    float* out = (float*)d_out;

    const int buildk_smem = (6*NORD*TSTRIDE + 2*NORD*NORD) * (int)sizeof(float); // 137216
    cudaFuncSetAttribute(buildk_kernel, cudaFuncAttributeMaxDynamicSharedMemorySize, buildk_smem);

    buildk_kernel<<<NCHAIN + 16, 256, buildk_smem>>>(A, Bv, E, W, bm);
    gemm1_kernel<<<dim3(MPAD/128, TSPLIT), 128>>>(x);
    fuse_kernel<<<MPAD/64, 256>>>(aw, ab);
    gemm2_kernel<<<dim3(MPAD/64, 6), 128>>>(out, aw, ab);
}